// round 9
// baseline (speedup 1.0000x reference)
#include <cuda_runtime.h>

// SSIM fully-fused, smem-free kernel for GB300 (sm_103a).
// R9 = R7 resource point (full unroll, STRIP_H=16, <=128 regs, 4 CTA/SM)
//    + explicit double-buffered row loads (load->use distance = full body)
//    + mid-sum scalar horizontal filters (kills packed-shift MOVs)
//    + scalar u / mu / final math with immediate constants.
//
// Algebra (scale-cancelled): with S = 3x3 sum, u = S - 9*center,
//   num = (2*Sx*Sy + 81*C1) * (2*Uxy + 729*C2)
//   den = (Sx^2 + Sy^2 + 81*C1) * (Uss + 729*C2),  Uss = Uxx + Uyy (merged)

#define IMG_H 512
#define IMG_W 960
#define OUT_H 508
#define OUT_W 956
#define W4    (IMG_W / 4)

#define NTHREADS 128          // 32 lanes wide x 4 strips
#define STRIP_H 16
#define TILE_W 128            // 32 lanes x 4 cols
#define TILE_H 64             // 4 strips x 16 rows

#define C1S (8.1e-3f)         // 81 * 0.01^2
#define C2S (0.6561f)         // 729 * 0.03^2

typedef unsigned long long u64;

__device__ __forceinline__ u64 PK(float lo, float hi) {
    u64 r; asm("mov.b64 %0, {%1, %2};" : "=l"(r) : "f"(lo), "f"(hi)); return r;
}
__device__ __forceinline__ void UPK(u64 a, float& lo, float& hi) {
    asm("mov.b64 {%0, %1}, %2;" : "=f"(lo), "=f"(hi) : "l"(a));
}
__device__ __forceinline__ u64 PADD(u64 a, u64 b) {
    u64 r; asm("add.rn.f32x2 %0, %1, %2;" : "=l"(r) : "l"(a), "l"(b)); return r;
}
__device__ __forceinline__ u64 PMUL(u64 a, u64 b) {
    u64 r; asm("mul.rn.f32x2 %0, %1, %2;" : "=l"(r) : "l"(a), "l"(b)); return r;
}
__device__ __forceinline__ u64 PFMA(u64 a, u64 b, u64 c) {
    u64 r; asm("fma.rn.f32x2 %0, %1, %2, %3;" : "=l"(r) : "l"(a), "l"(b), "l"(c)); return r;
}
#define PREF_L2(p) asm volatile("prefetch.global.L2 [%0];" :: "l"(p))

struct St {
    // stage-1 (prev, pairsum) vertical 3-sum state, packed
    u64 hx0p, hx0s, hx1p, hx1s, hx2p, hx2s;
    u64 hy0p, hy0s, hy1p, hy1s, hy2p, hy2s;
    // stage-2 (prev, pairsum), packed (merged ss channel + xy channel)
    u64 Hss0p, Hss0s, Hss1p, Hss1s;
    u64 Hxy0p, Hxy0s, Hxy1p, Hxy1s;
    // previous-row center scalars (cols 1..6 of the 8-float window)
    float px1, px2, px3, px4, px5, px6;
    float py1, py2, py3, py4, py5, py6;
    // mu sums (scalar, one-row history): S at cols 1..4
    float mx0, mx1, mx2, mx3, my0, my1, my2, my3;
};

// PHASE 0: h-sums + stage-1 accumulate + centers (rows 0,1)
// PHASE 1: + stage-1 S, u, products, stage-2 h-sums (rows 2,3)
// PHASE 2: full, produces output float4
template<int PHASE>
__device__ __forceinline__ void step(St& s,
    float4 xa, float4 xb, float4 ya, float4 yb, float4& out)
{
    // ---- stage-1 horizontal 3-sums via mid-sum identity (scalar) ----
    float mxa = xa.y + xa.z;   // a1+a2
    float mxb = xa.w + xb.x;   // a3+a4
    float mxc = xb.y + xb.z;   // a5+a6
    u64 nhx0 = PK(xa.x + mxa, mxa + xa.w);   // h(0), h(1)
    u64 nhx1 = PK(xa.z + mxb, mxb + xb.y);   // h(2), h(3)
    u64 nhx2 = PK(xb.x + mxc, mxc + xb.w);   // h(4), h(5)

    float mya = ya.y + ya.z;
    float myb = ya.w + yb.x;
    float myc = yb.y + yb.z;
    u64 nhy0 = PK(ya.x + mya, mya + ya.w);
    u64 nhy1 = PK(ya.z + myb, myb + yb.y);
    u64 nhy2 = PK(yb.x + myc, myc + yb.w);

    if (PHASE >= 1) {
        // stage-1 vertical 3-sums (packed): S = h_t + (h_{t-1}+h_{t-2})
        u64 Sx0 = PADD(nhx0, s.hx0s);
        u64 Sx1 = PADD(nhx1, s.hx1s);
        u64 Sx2 = PADD(nhx2, s.hx2s);
        u64 Sy0 = PADD(nhy0, s.hy0s);
        u64 Sy1 = PADD(nhy1, s.hy1s);
        u64 Sy2 = PADD(nhy2, s.hy2s);

        float Sx0l, Sx0h, Sx1l, Sx1h, Sx2l, Sx2h;
        float Sy0l, Sy0h, Sy1l, Sy1h, Sy2l, Sy2h;
        UPK(Sx0, Sx0l, Sx0h); UPK(Sx1, Sx1l, Sx1h); UPK(Sx2, Sx2l, Sx2h);
        UPK(Sy0, Sy0l, Sy0h); UPK(Sy1, Sy1l, Sy1h); UPK(Sy2, Sy2l, Sy2h);

        // u = S - 9*center (scalar FFMA, immediate -9; centers = prev row)
        u64 ux0 = PK(fmaf(s.px1, -9.0f, Sx0l), fmaf(s.px2, -9.0f, Sx0h));
        u64 ux1 = PK(fmaf(s.px3, -9.0f, Sx1l), fmaf(s.px4, -9.0f, Sx1h));
        u64 ux2 = PK(fmaf(s.px5, -9.0f, Sx2l), fmaf(s.px6, -9.0f, Sx2h));
        u64 uy0 = PK(fmaf(s.py1, -9.0f, Sy0l), fmaf(s.py2, -9.0f, Sy0h));
        u64 uy1 = PK(fmaf(s.py3, -9.0f, Sy1l), fmaf(s.py4, -9.0f, Sy1h));
        u64 uy2 = PK(fmaf(s.py5, -9.0f, Sy2l), fmaf(s.py6, -9.0f, Sy2h));

        // products (packed): ss = ux^2 + uy^2 (merged), xy = ux*uy
        u64 tssP0 = PFMA(uy0, uy0, PMUL(ux0, ux0));
        u64 tssP1 = PFMA(uy1, uy1, PMUL(ux1, ux1));
        u64 tssP2 = PFMA(uy2, uy2, PMUL(ux2, ux2));
        u64 txyP0 = PMUL(ux0, uy0);
        u64 txyP1 = PMUL(ux1, uy1);
        u64 txyP2 = PMUL(ux2, uy2);

        // stage-2 horizontal 3-sums via mid-sum identity (scalar halves)
        float s0, s1, s2, s3, s4, s5, x0, x1, x2, x3, x4, x5;
        UPK(tssP0, s0, s1); UPK(tssP1, s2, s3); UPK(tssP2, s4, s5);
        UPK(txyP0, x0, x1); UPK(txyP1, x2, x3); UPK(txyP2, x4, x5);

        float mS0 = s1 + s2, mS1 = s3 + s4;
        u64 nHss0 = PK(s0 + mS0, mS0 + s3);
        u64 nHss1 = PK(s2 + mS1, mS1 + s5);
        float mX0 = x1 + x2, mX1 = x3 + x4;
        u64 nHxy0 = PK(x0 + mX0, mX0 + x3);
        u64 nHxy1 = PK(x2 + mX1, mX1 + x5);

        if (PHASE == 2) {
            // stage-2 vertical 3-sums
            u64 Uss0 = PADD(nHss0, s.Hss0s);
            u64 Uss1 = PADD(nHss1, s.Hss1s);
            u64 Uxy0 = PADD(nHxy0, s.Hxy0s);
            u64 Uxy1 = PADD(nHxy1, s.Hxy1s);

            float US0, US1, US2, US3, UX0, UX1, UX2, UX3;
            UPK(Uss0, US0, US1); UPK(Uss1, US2, US3);
            UPK(Uxy0, UX0, UX1); UPK(Uxy1, UX2, UX3);

            // scalar SSIM formula per output column
            float t0 = s.mx0 * s.my0, t1 = s.mx1 * s.my1;
            float t2 = s.mx2 * s.my2, t3 = s.mx3 * s.my3;
            float n1_0 = fmaf(t0, 2.0f, C1S), n1_1 = fmaf(t1, 2.0f, C1S);
            float n1_2 = fmaf(t2, 2.0f, C1S), n1_3 = fmaf(t3, 2.0f, C1S);
            float d1_0 = fmaf(s.my0, s.my0, fmaf(s.mx0, s.mx0, C1S));
            float d1_1 = fmaf(s.my1, s.my1, fmaf(s.mx1, s.mx1, C1S));
            float d1_2 = fmaf(s.my2, s.my2, fmaf(s.mx2, s.mx2, C1S));
            float d1_3 = fmaf(s.my3, s.my3, fmaf(s.mx3, s.mx3, C1S));
            float n2_0 = fmaf(UX0, 2.0f, C2S), n2_1 = fmaf(UX1, 2.0f, C2S);
            float n2_2 = fmaf(UX2, 2.0f, C2S), n2_3 = fmaf(UX3, 2.0f, C2S);
            float d2_0 = US0 + C2S, d2_1 = US1 + C2S;
            float d2_2 = US2 + C2S, d2_3 = US3 + C2S;

            out.x = fminf(fmaxf(1.0f - __fdividef(n1_0 * n2_0, d1_0 * d2_0), 0.0f), 2.0f);
            out.y = fminf(fmaxf(1.0f - __fdividef(n1_1 * n2_1, d1_1 * d2_1), 0.0f), 2.0f);
            out.z = fminf(fmaxf(1.0f - __fdividef(n1_2 * n2_2, d1_2 * d2_2), 0.0f), 2.0f);
            out.w = fminf(fmaxf(1.0f - __fdividef(n1_3 * n2_3, d1_3 * d2_3), 0.0f), 2.0f);
        }

        // stage-2 accumulator updates
        s.Hss0s = PADD(nHss0, s.Hss0p);  s.Hss0p = nHss0;
        s.Hss1s = PADD(nHss1, s.Hss1p);  s.Hss1p = nHss1;
        s.Hxy0s = PADD(nHxy0, s.Hxy0p);  s.Hxy0p = nHxy0;
        s.Hxy1s = PADD(nHxy1, s.Hxy1p);  s.Hxy1p = nHxy1;

        // mu sums for next row's output: S at cols 1..4 (scalar renames)
        s.mx0 = Sx0h; s.mx1 = Sx1l; s.mx2 = Sx1h; s.mx3 = Sx2l;
        s.my0 = Sy0h; s.my1 = Sy1l; s.my2 = Sy1h; s.my3 = Sy2l;
    }

    // stage-1 accumulator updates (every row)
    s.hx0s = PADD(nhx0, s.hx0p);  s.hx0p = nhx0;
    s.hx1s = PADD(nhx1, s.hx1p);  s.hx1p = nhx1;
    s.hx2s = PADD(nhx2, s.hx2p);  s.hx2p = nhx2;
    s.hy0s = PADD(nhy0, s.hy0p);  s.hy0p = nhy0;
    s.hy1s = PADD(nhy1, s.hy1p);  s.hy1p = nhy1;
    s.hy2s = PADD(nhy2, s.hy2p);  s.hy2p = nhy2;

    // centers for the next stage-1 row (scalar renames)
    s.px1 = xa.y; s.px2 = xa.z; s.px3 = xa.w;
    s.px4 = xb.x; s.px5 = xb.y; s.px6 = xb.z;
    s.py1 = ya.y; s.py2 = ya.z; s.py3 = ya.w;
    s.py4 = yb.x; s.py5 = yb.y; s.py6 = yb.z;
}

__global__ __launch_bounds__(NTHREADS, 4)
void ssim_kernel(const float* __restrict__ X,
                 const float* __restrict__ Y,
                 float* __restrict__ O)
{
    const int tid   = threadIdx.x;
    const int lane  = tid & 31;
    const int strip = tid >> 5;
    const int img   = blockIdx.z;
    const int oy0   = blockIdx.y * TILE_H + strip * STRIP_H;
    const int ox    = blockIdx.x * TILE_W + 4 * lane;
    const int cx    = min(ox, IMG_W - 8);   // clamp reads; outputs masked
    const bool col_ok = (ox < OUT_W);

    const float4* __restrict__ X4 =
        (const float4*)(X + (size_t)img * (IMG_H * IMG_W) + cx);
    const float4* __restrict__ Y4 =
        (const float4*)(Y + (size_t)img * (IMG_H * IMG_W) + cx);
    float* __restrict__ Ob = O + (size_t)img * (OUT_H * OUT_W) + ox;

    St s;
    s.hx0p = s.hx0s = s.hx1p = s.hx1s = s.hx2p = s.hx2s = 0;
    s.hy0p = s.hy0s = s.hy1p = s.hy1s = s.hy2p = s.hy2s = 0;
    s.Hss0p = s.Hss0s = s.Hss1p = s.Hss1s = 0;
    s.Hxy0p = s.Hxy0s = s.Hxy1p = s.Hxy1s = 0;
    s.px1 = s.px2 = s.px3 = s.px4 = s.px5 = s.px6 = 0.0f;
    s.py1 = s.py2 = s.py3 = s.py4 = s.py5 = s.py6 = 0.0f;
    s.mx0 = s.mx1 = s.mx2 = s.mx3 = 0.0f;
    s.my0 = s.my1 = s.my2 = s.my3 = 0.0f;

    // ---- double-buffered quads: load row 0 now ----
    int ro = oy0 * W4;
    float4 cxa = __ldg(X4 + ro), cxb = __ldg(X4 + ro + 1);
    float4 cya = __ldg(Y4 + ro), cyb = __ldg(Y4 + ro + 1);

    float4 out;
    #pragma unroll
    for (int t = 0; t < STRIP_H + 4; ++t) {
        // issue next row's loads first (load->use distance = full body)
        float4 nxa, nxb, nya, nyb;
        if (t + 1 < STRIP_H + 4) {
            const int gy1 = min(oy0 + t + 1, IMG_H - 1);
            const int r1  = gy1 * W4;
            nxa = __ldg(X4 + r1); nxb = __ldg(X4 + r1 + 1);
            nya = __ldg(Y4 + r1); nyb = __ldg(Y4 + r1 + 1);
            // L2 prefetch 5 rows ahead
            const int pgy = min(oy0 + t + 5, IMG_H - 1);
            PREF_L2((const float*)(X4 + pgy * W4));
            PREF_L2((const float*)(Y4 + pgy * W4));
        }

        if (t < 2)      step<0>(s, cxa, cxb, cya, cyb, out);
        else if (t < 4) step<1>(s, cxa, cxb, cya, cyb, out);
        else {
            step<2>(s, cxa, cxb, cya, cyb, out);
            const int oy = oy0 + t - 4;
            if (col_ok && oy < OUT_H) {
                *(float4*)(Ob + (size_t)oy * OUT_W) = out;
            }
        }

        cxa = nxa; cxb = nxb; cya = nya; cyb = nyb;
    }
}

extern "C" void kernel_launch(void* const* d_in, const int* in_sizes, int n_in,
                              void* d_out, int out_size)
{
    const float* x = (const float*)d_in[0];
    const float* y = (const float*)d_in[1];
    float* o = (float*)d_out;

    dim3 grid((OUT_W + TILE_W - 1) / TILE_W,   // 8
              (OUT_H + TILE_H - 1) / TILE_H,   // 8
              48);                             // 16 batch * 3 channels
    ssim_kernel<<<grid, NTHREADS>>>(x, y, o);
}

// round 10
// speedup vs baseline: 1.1362x; 1.1362x over previous
#include <cuda_runtime.h>

// SSIM fully-fused, smem-free kernel for GB300 (sm_103a).
// R10: 2 output columns per thread (halved per-thread state -> 6 CTAs/SM,
// 24 warps) + R9's scalar mid-sum horizontal filters (low MOV count) +
// packed f32x2 accumulators. Full unroll, STRIP_H=16, no double-buffering.
//
// Algebra (scale-cancelled): with S = 3x3 sum, u = S - 9*center,
//   num = (2*Sx*Sy + 81*C1) * (2*Uxy + 729*C2)
//   den = (Sx^2 + Sy^2 + 81*C1) * (Uss + 729*C2),  Uss = Uxx + Uyy (merged)

#define IMG_H 512
#define IMG_W 960
#define OUT_H 508
#define OUT_W 956
#define W2    (IMG_W / 2)     // row stride in float2 units

#define NTHREADS 128          // 32 lanes x 4 strips
#define STRIP_H 16
#define TILE_W 64             // 32 lanes x 2 cols
#define TILE_H 64             // 4 strips x 16 rows

#define C1S (8.1e-3f)         // 81 * 0.01^2
#define C2S (0.6561f)         // 729 * 0.03^2

typedef unsigned long long u64;

__device__ __forceinline__ u64 PK(float lo, float hi) {
    u64 r; asm("mov.b64 %0, {%1, %2};" : "=l"(r) : "f"(lo), "f"(hi)); return r;
}
__device__ __forceinline__ void UPK(u64 a, float& lo, float& hi) {
    asm("mov.b64 {%0, %1}, %2;" : "=f"(lo), "=f"(hi) : "l"(a));
}
__device__ __forceinline__ u64 PADD(u64 a, u64 b) {
    u64 r; asm("add.rn.f32x2 %0, %1, %2;" : "=l"(r) : "l"(a), "l"(b)); return r;
}
__device__ __forceinline__ u64 PMUL(u64 a, u64 b) {
    u64 r; asm("mul.rn.f32x2 %0, %1, %2;" : "=l"(r) : "l"(a), "l"(b)); return r;
}
__device__ __forceinline__ u64 PFMA(u64 a, u64 b, u64 c) {
    u64 r; asm("fma.rn.f32x2 %0, %1, %2, %3;" : "=l"(r) : "l"(a), "l"(b), "l"(c)); return r;
}
#define PREF_L2(p) asm volatile("prefetch.global.L2 [%0];" :: "l"(p))

struct St {
    // stage-1 (prev, pairsum) vertical 3-sum state, packed: cols (0,1),(2,3)
    u64 hx0p, hx0s, hx1p, hx1s;
    u64 hy0p, hy0s, hy1p, hy1s;
    // stage-2 (prev, pairsum), packed: output cols (0,1)
    u64 Hssp, Hsss, Hxyp, Hxys;
    // previous-row centers (input cols 1..4)
    float px1, px2, px3, px4;
    float py1, py2, py3, py4;
    // mu sums (S at cols 1,2), one-row history
    float mx0, mx1, my0, my1;
};

// PHASE 0: h-sums + stage-1 accumulate + centers (rows 0,1)
// PHASE 1: + stage-1 S, u, products, stage-2 h-sums (rows 2,3)
// PHASE 2: full, produces output float2
template<int PHASE>
__device__ __forceinline__ void step(St& s,
    float2 a0, float2 a1, float2 a2,
    float2 b0, float2 b1, float2 b2, float2& out)
{
    // input cols 0..5: x = {a0.x,a0.y,a1.x,a1.y,a2.x,a2.y}
    // stage-1 horizontal 3-sums at cols 0..3 via mid-sum identity
    float mxa = a0.y + a1.x;              // x1+x2
    float mxb = a1.y + a2.x;              // x3+x4
    u64 nhx0 = PK(a0.x + mxa, mxa + a1.y);   // h(0), h(1)
    u64 nhx1 = PK(a1.x + mxb, mxb + a2.y);   // h(2), h(3)

    float mya = b0.y + b1.x;
    float myb = b1.y + b2.x;
    u64 nhy0 = PK(b0.x + mya, mya + b1.y);
    u64 nhy1 = PK(b1.x + myb, myb + b2.y);

    if (PHASE >= 1) {
        // stage-1 vertical 3-sums (packed)
        u64 Sx0 = PADD(nhx0, s.hx0s);
        u64 Sx1 = PADD(nhx1, s.hx1s);
        u64 Sy0 = PADD(nhy0, s.hy0s);
        u64 Sy1 = PADD(nhy1, s.hy1s);

        float Sx0l, Sx0h, Sx1l, Sx1h, Sy0l, Sy0h, Sy1l, Sy1h;
        UPK(Sx0, Sx0l, Sx0h); UPK(Sx1, Sx1l, Sx1h);
        UPK(Sy0, Sy0l, Sy0h); UPK(Sy1, Sy1l, Sy1h);

        // u = S - 9*center (scalar FFMA with immediate; centers = prev row)
        u64 UXa = PK(fmaf(s.px1, -9.0f, Sx0l), fmaf(s.px2, -9.0f, Sx0h));
        u64 UXb = PK(fmaf(s.px3, -9.0f, Sx1l), fmaf(s.px4, -9.0f, Sx1h));
        u64 UYa = PK(fmaf(s.py1, -9.0f, Sy0l), fmaf(s.py2, -9.0f, Sy0h));
        u64 UYb = PK(fmaf(s.py3, -9.0f, Sy1l), fmaf(s.py4, -9.0f, Sy1h));

        // products (packed): ss = ux^2 + uy^2 (merged), xy = ux*uy
        u64 tssa = PFMA(UYa, UYa, PMUL(UXa, UXa));
        u64 tssb = PFMA(UYb, UYb, PMUL(UXb, UXb));
        u64 txya = PMUL(UXa, UYa);
        u64 txyb = PMUL(UXb, UYb);

        // stage-2 horizontal 3-sums (scalar mid-sum) for output cols 0,1
        float t0, t1, t2, t3, z0, z1, z2, z3;
        UPK(tssa, t0, t1); UPK(tssb, t2, t3);
        UPK(txya, z0, z1); UPK(txyb, z2, z3);
        float mT = t1 + t2;
        u64 nHss = PK(t0 + mT, mT + t3);
        float mZ = z1 + z2;
        u64 nHxy = PK(z0 + mZ, mZ + z3);

        if (PHASE == 2) {
            // stage-2 vertical 3-sums
            u64 Uss = PADD(nHss, s.Hsss);
            u64 Uxy = PADD(nHxy, s.Hxys);

            float US0, US1, UXY0, UXY1;
            UPK(Uss, US0, US1); UPK(Uxy, UXY0, UXY1);

            // scalar SSIM per output column
            float n1_0 = fmaf(s.mx0 * s.my0, 2.0f, C1S);
            float n1_1 = fmaf(s.mx1 * s.my1, 2.0f, C1S);
            float d1_0 = fmaf(s.my0, s.my0, fmaf(s.mx0, s.mx0, C1S));
            float d1_1 = fmaf(s.my1, s.my1, fmaf(s.mx1, s.mx1, C1S));
            float n2_0 = fmaf(UXY0, 2.0f, C2S);
            float n2_1 = fmaf(UXY1, 2.0f, C2S);
            float d2_0 = US0 + C2S;
            float d2_1 = US1 + C2S;

            out.x = fminf(fmaxf(1.0f - __fdividef(n1_0 * n2_0, d1_0 * d2_0), 0.0f), 2.0f);
            out.y = fminf(fmaxf(1.0f - __fdividef(n1_1 * n2_1, d1_1 * d2_1), 0.0f), 2.0f);
        }

        // stage-2 accumulator updates
        s.Hsss = PADD(nHss, s.Hssp);  s.Hssp = nHss;
        s.Hxys = PADD(nHxy, s.Hxyp);  s.Hxyp = nHxy;

        // mu sums for next row's output: S at cols 1,2
        s.mx0 = Sx0h; s.mx1 = Sx1l;
        s.my0 = Sy0h; s.my1 = Sy1l;
    }

    // stage-1 accumulator updates (every row)
    s.hx0s = PADD(nhx0, s.hx0p);  s.hx0p = nhx0;
    s.hx1s = PADD(nhx1, s.hx1p);  s.hx1p = nhx1;
    s.hy0s = PADD(nhy0, s.hy0p);  s.hy0p = nhy0;
    s.hy1s = PADD(nhy1, s.hy1p);  s.hy1p = nhy1;

    // centers for the next stage-1 row (input cols 1..4)
    s.px1 = a0.y; s.px2 = a1.x; s.px3 = a1.y; s.px4 = a2.x;
    s.py1 = b0.y; s.py2 = b1.x; s.py3 = b1.y; s.py4 = b2.x;
}

__global__ __launch_bounds__(NTHREADS, 6)
void ssim_kernel(const float* __restrict__ X,
                 const float* __restrict__ Y,
                 float* __restrict__ O)
{
    const int tid   = threadIdx.x;
    const int lane  = tid & 31;
    const int strip = tid >> 5;
    const int img   = blockIdx.z;
    const int oy0   = blockIdx.y * TILE_H + strip * STRIP_H;
    const int ox    = blockIdx.x * TILE_W + 2 * lane;
    const int cx    = min(ox, IMG_W - 6);   // clamp reads (even); mask outputs
    const bool col_ok = (ox < OUT_W);

    const float2* __restrict__ X2 =
        (const float2*)(X + (size_t)img * (IMG_H * IMG_W) + cx);
    const float2* __restrict__ Y2 =
        (const float2*)(Y + (size_t)img * (IMG_H * IMG_W) + cx);
    float* __restrict__ Ob = O + (size_t)img * (OUT_H * OUT_W) + ox;

    St s;
    s.hx0p = s.hx0s = s.hx1p = s.hx1s = 0;
    s.hy0p = s.hy0s = s.hy1p = s.hy1s = 0;
    s.Hssp = s.Hsss = s.Hxyp = s.Hxys = 0;
    s.px1 = s.px2 = s.px3 = s.px4 = 0.0f;
    s.py1 = s.py2 = s.py3 = s.py4 = 0.0f;
    s.mx0 = s.mx1 = s.my0 = s.my1 = 0.0f;

    float2 out;
    #pragma unroll
    for (int t = 0; t < STRIP_H + 4; ++t) {
        const int gy = min(oy0 + t, IMG_H - 1);
        const int ro = gy * W2;

        float2 a0 = __ldg(X2 + ro), a1 = __ldg(X2 + ro + 1), a2 = __ldg(X2 + ro + 2);
        float2 b0 = __ldg(Y2 + ro), b1 = __ldg(Y2 + ro + 1), b2 = __ldg(Y2 + ro + 2);

        if (t + 4 < STRIP_H + 4) {
            const int pgy = min(oy0 + t + 4, IMG_H - 1);
            PREF_L2((const float*)(X2 + pgy * W2));
            PREF_L2((const float*)(Y2 + pgy * W2));
        }

        if (t < 2)      step<0>(s, a0, a1, a2, b0, b1, b2, out);
        else if (t < 4) step<1>(s, a0, a1, a2, b0, b1, b2, out);
        else {
            step<2>(s, a0, a1, a2, b0, b1, b2, out);
            const int oy = oy0 + t - 4;
            if (col_ok && oy < OUT_H) {
                *(float2*)(Ob + (size_t)oy * OUT_W) = out;
            }
        }
    }
}

extern "C" void kernel_launch(void* const* d_in, const int* in_sizes, int n_in,
                              void* d_out, int out_size)
{
    const float* x = (const float*)d_in[0];
    const float* y = (const float*)d_in[1];
    float* o = (float*)d_out;

    dim3 grid((OUT_W + TILE_W - 1) / TILE_W,   // 15
              (OUT_H + TILE_H - 1) / TILE_H,   // 8
              48);                             // 16 batch * 3 channels
    ssim_kernel<<<grid, NTHREADS>>>(x, y, o);
}